// round 1
// baseline (speedup 1.0000x reference)
#include <cuda_runtime.h>
#include <math.h>

#define N_NODES 50000
#define N_EDGES 600000
#define N_GRAPHS 64

__device__ __constant__ float c_dummy; // none needed; constants below

static __device__ float g_fa[N_NODES * 64];
static __device__ float g_fb[N_NODES * 64];
static __device__ float g_F [N_NODES * 64];

#define INV_S3 0.57735026918962576f   /* 1/sqrt(3) */
#define INV_S2 0.70710678118654752f   /* 1/sqrt(2) */
#define NORM_S 0.044194173824159216f  /* 1/sqrt(512) */
#define NORM_V 0.036084391824351615f  /* 1/sqrt(768) */
#define INV_LIN_IN 0.35355339059327373f /* 1/sqrt(8) */
#define INV_LIN_OUT 0.25f

// ---------------------------------------------------------------------------
// Input projection: x[N,32] -> f[N,64]  (s[16] | v[16][3] at 16+w*3+i)
// ---------------------------------------------------------------------------
__global__ __launch_bounds__(256) void proj_kernel(
    const float* __restrict__ x, const float* __restrict__ w0,
    const float* __restrict__ w1, float* __restrict__ f)
{
    __shared__ float sw0[128], sw1[128];
    int t = threadIdx.x;
    if (t < 128) sw0[t] = w0[t];
    else         sw1[t - 128] = w1[t - 128];
    __syncthreads();

    int n = blockIdx.x * 256 + t;
    if (n >= N_NODES) return;

    float xin[32];
    #pragma unroll
    for (int i = 0; i < 8; ++i)
        ((float4*)xin)[i] = ((const float4*)(x + n * 32))[i];

    float s[16];
    #pragma unroll
    for (int w = 0; w < 16; ++w) s[w] = 0.f;
    #pragma unroll
    for (int u = 0; u < 8; ++u) {
        float xu = xin[u];
        #pragma unroll
        for (int w = 0; w < 16; ++w) s[w] += xu * sw0[u * 16 + w];
    }
    float vv[48];
    #pragma unroll
    for (int q = 0; q < 48; ++q) vv[q] = 0.f;
    #pragma unroll
    for (int u = 0; u < 8; ++u) {
        float x0 = xin[8 + u * 3 + 0];
        float x1 = xin[8 + u * 3 + 1];
        float x2 = xin[8 + u * 3 + 2];
        #pragma unroll
        for (int w = 0; w < 16; ++w) {
            float wt = sw1[u * 16 + w];
            vv[w * 3 + 0] += x0 * wt;
            vv[w * 3 + 1] += x1 * wt;
            vv[w * 3 + 2] += x2 * wt;
        }
    }
    float* fn = f + n * 64;
    #pragma unroll
    for (int w = 0; w < 16; ++w) fn[w] = s[w] * INV_LIN_IN;
    #pragma unroll
    for (int q = 0; q < 48; ++q) fn[16 + q] = vv[q] * INV_LIN_IN;
}

// ---------------------------------------------------------------------------
// Aggregation: F[row[e]] += f[col[e]]  (64 floats per edge, atomics into L2)
// 16 threads per edge, each does a float4 load + 4 atomicAdds
// ---------------------------------------------------------------------------
__global__ __launch_bounds__(256) void agg_kernel(
    const float* __restrict__ f, const int* __restrict__ row,
    const int* __restrict__ col, float* __restrict__ F)
{
    unsigned idx = blockIdx.x * 256u + threadIdx.x;
    unsigned e = idx >> 4, q = idx & 15u;
    if (e >= N_EDGES) return;
    int c = __ldg(col + e);
    int r = __ldg(row + e);
    float4 val = ((const float4*)(f + (size_t)c * 64))[q];
    float* dst = F + (size_t)r * 64 + q * 4;
    atomicAdd(dst + 0, val.x);
    atomicAdd(dst + 1, val.y);
    atomicAdd(dst + 2, val.z);
    atomicAdd(dst + 3, val.w);
}

// ---------------------------------------------------------------------------
// Per-node tensor product + gate.
//   acc = TP(f[n], F[n]) ; f_out[n] = gate(acc)
// Thread t = v*16 + w holds W[path][u][v][w] for u=0..15 in registers (80 regs),
// reused across all nodes the block processes.
// Stage 1 per node: 11 left-contractions t*[v,w] -> shared memory.
// Stage 2 per node: 64 outputs, 4 threads each (v split), shuffle-reduced.
// ---------------------------------------------------------------------------
#define TP_BATCH 4
__global__ __launch_bounds__(256) void tp_gate_kernel(
    const float* __restrict__ f, const float* __restrict__ Fg,
    const float* __restrict__ W, float* __restrict__ fout)
{
    const int t = threadIdx.x; // t = v*16 + w
    float w0r[16], w1r[16], w2r[16], w3r[16], w4r[16];
    #pragma unroll
    for (int u = 0; u < 16; ++u) {
        w0r[u] = __ldg(W + 0 * 4096 + u * 256 + t);
        w1r[u] = __ldg(W + 1 * 4096 + u * 256 + t);
        w2r[u] = __ldg(W + 2 * 4096 + u * 256 + t);
        w3r[u] = __ldg(W + 3 * 4096 + u * 256 + t);
        w4r[u] = __ldg(W + 4 * 4096 + u * 256 + t);
    }

    __shared__ float sf[TP_BATCH][128];      // [0..64) = f[n], [64..128) = F[n]
    __shared__ float ts[TP_BATCH][11][256];  // 0:t0 1:t1 2-4:t2k 5-7:t3i 8-10:t4i
    __shared__ float outb[TP_BATCH][64];

    for (int base = blockIdx.x * TP_BATCH; base < N_NODES;
         base += gridDim.x * TP_BATCH) {
        int nb = N_NODES - base; if (nb > TP_BATCH) nb = TP_BATCH;

        // load features
        for (int idx = t; idx < TP_BATCH * 128; idx += 256) {
            int nn = idx >> 7, c = idx & 127;
            if (nn < nb) {
                size_t n = (size_t)(base + nn);
                sf[nn][c] = (c < 64) ? f[n * 64 + c] : Fg[n * 64 + (c - 64)];
            }
        }
        __syncthreads();

        // ---- stage 1: left contractions ----
        #pragma unroll
        for (int nn = 0; nn < TP_BATCH; ++nn) {
            if (nn < nb) {
                const float* s1 = sf[nn];
                const float* v1 = sf[nn] + 16;
                float a0 = 0, a1 = 0;
                float a2x = 0, a2y = 0, a2z = 0;
                float a3x = 0, a3y = 0, a3z = 0;
                float a4x = 0, a4y = 0, a4z = 0;
                #pragma unroll
                for (int u = 0; u < 16; ++u) {
                    float su = s1[u];
                    float vx = v1[u * 3 + 0], vy = v1[u * 3 + 1], vz = v1[u * 3 + 2];
                    a0 += su * w0r[u];
                    a1 += su * w1r[u];
                    a2x += vx * w2r[u]; a2y += vy * w2r[u]; a2z += vz * w2r[u];
                    a3x += vx * w3r[u]; a3y += vy * w3r[u]; a3z += vz * w3r[u];
                    a4x += vx * w4r[u]; a4y += vy * w4r[u]; a4z += vz * w4r[u];
                }
                ts[nn][0][t] = a0;  ts[nn][1][t] = a1;
                ts[nn][2][t] = a2x; ts[nn][3][t] = a2y; ts[nn][4][t] = a2z;
                ts[nn][5][t] = a3x; ts[nn][6][t] = a3y; ts[nn][7][t] = a3z;
                ts[nn][8][t] = a4x; ts[nn][9][t] = a4y; ts[nn][10][t] = a4z;
            }
        }
        __syncthreads();

        // ---- stage 2: outputs ----
        const int o = t >> 2, q = t & 3;
        #pragma unroll
        for (int nn = 0; nn < TP_BATCH; ++nn) {
            if (nn < nb) {
                const float* S = sf[nn] + 64;
                const float* V = sf[nn] + 80;
                float acc = 0.f;
                if (o < 16) {
                    int w = o;
                    #pragma unroll
                    for (int dv = 0; dv < 4; ++dv) {
                        int v = q * 4 + dv;
                        acc += ts[nn][0][v * 16 + w] * S[v];
                        acc += INV_S3 * (ts[nn][5][v * 16 + w] * V[v * 3 + 0] +
                                         ts[nn][6][v * 16 + w] * V[v * 3 + 1] +
                                         ts[nn][7][v * 16 + w] * V[v * 3 + 2]);
                    }
                } else {
                    int q2 = o - 16;
                    int w = q2 / 3, k = q2 % 3;
                    int i = (k + 1) % 3, j = (k + 2) % 3; // cyc
                    #pragma unroll
                    for (int dv = 0; dv < 4; ++dv) {
                        int v = q * 4 + dv;
                        float p2 = ts[nn][1][v * 16 + w] * V[v * 3 + k];
                        float p3 = ts[nn][2 + k][v * 16 + w] * S[v];
                        float p5 = ts[nn][8 + i][v * 16 + w] * V[v * 3 + j]
                                 - ts[nn][8 + j][v * 16 + w] * V[v * 3 + i];
                        acc += p2 + p3 + INV_S2 * p5;
                    }
                }
                acc += __shfl_xor_sync(0xffffffffu, acc, 1);
                acc += __shfl_xor_sync(0xffffffffu, acc, 2);
                if (q == 0) outb[nn][o] = acc;
            }
        }
        __syncthreads();

        // ---- gate + writeback ----
        {
            int nn = t >> 6, oo = t & 63;
            if (nn < nb) {
                size_t n = (size_t)(base + nn);
                float r;
                if (oo < 16) {
                    float sp = NORM_S * outb[nn][oo];
                    float sg = 1.f / (1.f + expf(-sp));
                    r = sp * sg;
                } else {
                    int w = (oo - 16) / 3;
                    float sp = NORM_S * outb[nn][w];
                    float sg = 1.f / (1.f + expf(-sp));
                    r = NORM_V * outb[nn][oo] * sg;
                }
                fout[n * 64 + oo] = r;
            }
        }
        __syncthreads();
    }
}

// ---------------------------------------------------------------------------
// Readout: energy[g] = sum_n (s[n]·w_out) * 0.25   grouped by batch_idx
// ---------------------------------------------------------------------------
__global__ __launch_bounds__(256) void readout_kernel(
    const float* __restrict__ f, const int* __restrict__ batch,
    const float* __restrict__ w, float* __restrict__ out)
{
    __shared__ float acc[N_GRAPHS];
    __shared__ float sw[16];
    int t = threadIdx.x;
    if (t < N_GRAPHS) acc[t] = 0.f;
    if (t < 16) sw[t] = w[t];
    __syncthreads();
    int n = blockIdx.x * 256 + t;
    if (n < N_NODES) {
        const float* fn = f + (size_t)n * 64;
        float val = 0.f;
        #pragma unroll
        for (int u = 0; u < 16; ++u) val += fn[u] * sw[u];
        atomicAdd(&acc[batch[n]], val * INV_LIN_OUT);
    }
    __syncthreads();
    if (t < N_GRAPHS && acc[t] != 0.f) atomicAdd(out + t, acc[t]);
}

// ---------------------------------------------------------------------------
extern "C" void kernel_launch(void* const* d_in, const int* in_sizes, int n_in,
                              void* d_out, int out_size)
{
    const float* x      = (const float*)d_in[0];
    const int*   row    = (const int*)  d_in[1];
    const int*   col    = (const int*)  d_in[2];
    const int*   batch  = (const int*)  d_in[3];
    const float* w_in0  = (const float*)d_in[4];
    const float* w_in1  = (const float*)d_in[5];
    const float* tpw    = (const float*)d_in[6];
    const float* w_out0 = (const float*)d_in[7];
    float* out = (float*)d_out;

    float *fa, *fb, *Fg;
    cudaGetSymbolAddress((void**)&fa, g_fa);
    cudaGetSymbolAddress((void**)&fb, g_fb);
    cudaGetSymbolAddress((void**)&Fg, g_F);

    proj_kernel<<<(N_NODES + 255) / 256, 256>>>(x, w_in0, w_in1, fa);

    float* cur = fa;
    float* nxt = fb;
    for (int l = 0; l < 3; ++l) {
        cudaMemsetAsync(Fg, 0, (size_t)N_NODES * 64 * sizeof(float));
        agg_kernel<<<(N_EDGES * 16 + 255) / 256, 256>>>(cur, row, col, Fg);
        tp_gate_kernel<<<2048, 256>>>(cur, Fg, tpw + (size_t)l * 5 * 4096, nxt);
        float* tmp = cur; cur = nxt; nxt = tmp;
    }

    cudaMemsetAsync(out, 0, N_GRAPHS * sizeof(float));
    readout_kernel<<<(N_NODES + 255) / 256, 256>>>(cur, batch, w_out0, out);
}

// round 4
// speedup vs baseline: 1.2920x; 1.2920x over previous
#include <cuda_runtime.h>
#include <math.h>

#define N_NODES 50000
#define N_EDGES 600000
#define N_GRAPHS 64

static __device__ float g_fa[N_NODES * 64];
static __device__ float g_fb[N_NODES * 64];
static __device__ float g_F [N_NODES * 64];

#define INV_S3 0.57735026918962576f   /* 1/sqrt(3) */
#define INV_S2 0.70710678118654752f   /* 1/sqrt(2) */
#define NORM_S 0.044194173824159216f  /* 1/sqrt(512) */
#define NORM_V 0.036084391824351615f  /* 1/sqrt(768) */
#define INV_LIN_IN 0.35355339059327373f /* 1/sqrt(8) */
#define INV_LIN_OUT 0.25f

typedef unsigned long long u64;

// ---- packed fp32x2 helpers (sm_103a) --------------------------------------
__device__ __forceinline__ u64 pack2f(float a, float b) {
    u64 r;
    asm("mov.b64 %0, {%1, %2};" : "=l"(r) : "f"(a), "f"(b));
    return r;
}
__device__ __forceinline__ u64 ffma2(u64 a, u64 b, u64 c) {
    u64 d;
    asm("fma.rn.f32x2 %0, %1, %2, %3;" : "=l"(d) : "l"(a), "l"(b), "l"(c));
    return d;
}
__device__ __forceinline__ u64 addf2(u64 a, u64 b) {
    u64 d;
    asm("add.rn.f32x2 %0, %1, %2;" : "=l"(d) : "l"(a), "l"(b));
    return d;
}
__device__ __forceinline__ u64 neg2(u64 a) { return a ^ 0x8000000080000000ULL; }

// ---------------------------------------------------------------------------
// Input projection: x[N,32] -> f[N,64]  (s[16] | v[16][3] at 16+w*3+i)
// ---------------------------------------------------------------------------
__global__ __launch_bounds__(256) void proj_kernel(
    const float* __restrict__ x, const float* __restrict__ w0,
    const float* __restrict__ w1, float* __restrict__ f)
{
    __shared__ float sw0[128], sw1[128];
    int t = threadIdx.x;
    if (t < 128) sw0[t] = w0[t];
    else         sw1[t - 128] = w1[t - 128];
    __syncthreads();

    int n = blockIdx.x * 256 + t;
    if (n >= N_NODES) return;

    float xin[32];
    #pragma unroll
    for (int i = 0; i < 8; ++i)
        ((float4*)xin)[i] = ((const float4*)(x + n * 32))[i];

    float s[16];
    #pragma unroll
    for (int w = 0; w < 16; ++w) s[w] = 0.f;
    #pragma unroll
    for (int u = 0; u < 8; ++u) {
        float xu = xin[u];
        #pragma unroll
        for (int w = 0; w < 16; ++w) s[w] += xu * sw0[u * 16 + w];
    }
    float vv[48];
    #pragma unroll
    for (int q = 0; q < 48; ++q) vv[q] = 0.f;
    #pragma unroll
    for (int u = 0; u < 8; ++u) {
        float x0 = xin[8 + u * 3 + 0];
        float x1 = xin[8 + u * 3 + 1];
        float x2 = xin[8 + u * 3 + 2];
        #pragma unroll
        for (int w = 0; w < 16; ++w) {
            float wt = sw1[u * 16 + w];
            vv[w * 3 + 0] += x0 * wt;
            vv[w * 3 + 1] += x1 * wt;
            vv[w * 3 + 2] += x2 * wt;
        }
    }
    float* fn = f + n * 64;
    #pragma unroll
    for (int w = 0; w < 16; ++w) fn[w] = s[w] * INV_LIN_IN;
    #pragma unroll
    for (int q = 0; q < 48; ++q) fn[16 + q] = vv[q] * INV_LIN_IN;
}

// ---------------------------------------------------------------------------
// Aggregation: F[row[e]] += f[col[e]] via red.global.v4.f32.add (REDG.128)
// 16 threads per edge, each: one float4 load + one vector reduction
// ---------------------------------------------------------------------------
__global__ __launch_bounds__(256) void agg_kernel(
    const float* __restrict__ f, const int* __restrict__ row,
    const int* __restrict__ col, float* __restrict__ F)
{
    unsigned idx = blockIdx.x * 256u + threadIdx.x;
    unsigned e = idx >> 4, q = idx & 15u;
    if (e >= N_EDGES) return;
    int c = __ldg(col + e);
    int r = __ldg(row + e);
    float4 val = ((const float4*)(f + (size_t)c * 64))[q];
    float* dst = F + (size_t)r * 64 + q * 4;
    asm volatile("red.global.v4.f32.add [%0], {%1, %2, %3, %4};"
                 :: "l"(dst), "f"(val.x), "f"(val.y), "f"(val.z), "f"(val.w)
                 : "memory");
}

// ---------------------------------------------------------------------------
// Per-node TP + gate, packed: each block iteration handles 4 nodes as 2
// f32x2-packed pairs. Thread t = v*16 + w keeps W[path][u][v][w] duplicated
// into 64-bit (w,w) registers; stage-1 left contractions run as FFMA2 on
// node pairs loaded from interleaved smem via LDS.64.
// ---------------------------------------------------------------------------
#define TP_PAIRS 2   /* 4 nodes per block iteration; 50000 % 4 == 0 */
__global__ __launch_bounds__(256) void tp_gate_kernel(
    const float* __restrict__ f, const float* __restrict__ Fg,
    const float* __restrict__ W, float* __restrict__ fout)
{
    const int t = threadIdx.x; // t = v*16 + w

    u64 w0p[16], w1p[16], w2p[16], w3p[16], w4p[16];
    #pragma unroll
    for (int u = 0; u < 16; ++u) {
        float a = __ldg(W + 0 * 4096 + u * 256 + t); w0p[u] = pack2f(a, a);
        float b = __ldg(W + 1 * 4096 + u * 256 + t); w1p[u] = pack2f(b, b);
        float c = __ldg(W + 2 * 4096 + u * 256 + t); w2p[u] = pack2f(c, c);
        float d = __ldg(W + 3 * 4096 + u * 256 + t); w3p[u] = pack2f(d, d);
        float e = __ldg(W + 4 * 4096 + u * 256 + t); w4p[u] = pack2f(e, e);
    }
    const u64 INV3p = pack2f(INV_S3, INV_S3);
    const u64 INV2p = pack2f(INV_S2, INV_S2);

    // packed features: [pair][component 0..127] -> (nodeA, nodeB) in one u64
    __shared__ u64 sfp[TP_PAIRS][128];
    __shared__ u64 tsp[TP_PAIRS][11][256];  // 0:t0 1:t1 2-4:t2k 5-7:t3i 8-10:t4i
    __shared__ u64 outbp[TP_PAIRS][64];

    for (int base = blockIdx.x * (TP_PAIRS * 2); base < N_NODES;
         base += gridDim.x * (TP_PAIRS * 2)) {

        // ---- load features, interleaving node pairs ----
        {
            float* sfF = (float*)sfp;
            #pragma unroll
            for (int k = 0; k < TP_PAIRS; ++k) {
                int idx = t + k * 256;           // slot = p*256 + c*2 + s
                int p = idx >> 8;
                int c = (idx & 255) >> 1;
                int s = idx & 1;
                int node = base + p * 2 + s;
                sfF[idx] = (c < 64) ? f[(size_t)node * 64 + c]
                                    : Fg[(size_t)node * 64 + (c - 64)];
            }
        }
        __syncthreads();

        // ---- stage 1: 11 left contractions, packed over node pair ----
        for (int p = 0; p < TP_PAIRS; ++p) {
            const u64* fp = sfp[p];
            u64 a0 = 0, a1 = 0;
            u64 a2x = 0, a2y = 0, a2z = 0;
            u64 a3x = 0, a3y = 0, a3z = 0;
            u64 a4x = 0, a4y = 0, a4z = 0;
            #pragma unroll
            for (int u = 0; u < 16; ++u) {
                u64 su = fp[u];
                u64 vx = fp[16 + u * 3 + 0];
                u64 vy = fp[16 + u * 3 + 1];
                u64 vz = fp[16 + u * 3 + 2];
                a0  = ffma2(su, w0p[u], a0);
                a1  = ffma2(su, w1p[u], a1);
                a2x = ffma2(vx, w2p[u], a2x);
                a2y = ffma2(vy, w2p[u], a2y);
                a2z = ffma2(vz, w2p[u], a2z);
                a3x = ffma2(vx, w3p[u], a3x);
                a3y = ffma2(vy, w3p[u], a3y);
                a3z = ffma2(vz, w3p[u], a3z);
                a4x = ffma2(vx, w4p[u], a4x);
                a4y = ffma2(vy, w4p[u], a4y);
                a4z = ffma2(vz, w4p[u], a4z);
            }
            tsp[p][0][t] = a0;  tsp[p][1][t] = a1;
            tsp[p][2][t] = a2x; tsp[p][3][t] = a2y; tsp[p][4][t] = a2z;
            tsp[p][5][t] = a3x; tsp[p][6][t] = a3y; tsp[p][7][t] = a3z;
            tsp[p][8][t] = a4x; tsp[p][9][t] = a4y; tsp[p][10][t] = a4z;
        }
        __syncthreads();

        // ---- stage 2: 64 outputs x pair, 4 threads per output ----
        {
            const int o = t >> 2, q = t & 3;
            for (int p = 0; p < TP_PAIRS; ++p) {
                const u64* S = sfp[p] + 64;
                const u64* V = sfp[p] + 80;
                u64 acc = 0;
                if (o < 16) {
                    const int w = o;
                    u64 accd = 0;
                    #pragma unroll
                    for (int dv = 0; dv < 4; ++dv) {
                        int v = q * 4 + dv;
                        acc  = ffma2(tsp[p][0][v * 16 + w], S[v], acc);
                        accd = ffma2(tsp[p][5][v * 16 + w], V[v * 3 + 0], accd);
                        accd = ffma2(tsp[p][6][v * 16 + w], V[v * 3 + 1], accd);
                        accd = ffma2(tsp[p][7][v * 16 + w], V[v * 3 + 2], accd);
                    }
                    acc = ffma2(accd, INV3p, acc);
                } else {
                    const int q2 = o - 16;
                    const int w = q2 / 3, k = q2 % 3;
                    const int i = (k + 1) % 3, j = (k + 2) % 3;
                    u64 acc5 = 0;
                    #pragma unroll
                    for (int dv = 0; dv < 4; ++dv) {
                        int v = q * 4 + dv;
                        acc  = ffma2(tsp[p][1][v * 16 + w], V[v * 3 + k], acc);
                        acc  = ffma2(tsp[p][2 + k][v * 16 + w], S[v], acc);
                        acc5 = ffma2(tsp[p][8 + i][v * 16 + w], V[v * 3 + j], acc5);
                        acc5 = ffma2(neg2(tsp[p][8 + j][v * 16 + w]), V[v * 3 + i], acc5);
                    }
                    acc = ffma2(acc5, INV2p, acc);
                }
                acc = addf2(acc, __shfl_xor_sync(0xffffffffu, acc, 1));
                acc = addf2(acc, __shfl_xor_sync(0xffffffffu, acc, 2));
                if (q == 0) outbp[p][o] = acc;
            }
        }
        __syncthreads();

        // ---- gate + writeback: 4 nodes x 64 outputs = 256 threads ----
        {
            const int nn = t >> 6;          // node within group (0..3)
            const int p = nn >> 1, s = nn & 1;
            const int oo = t & 63;
            const float* obF = (const float*)outbp;
            float raw = obF[(p * 64 + oo) * 2 + s];
            float r;
            if (oo < 16) {
                float sp = NORM_S * raw;
                float sg = 1.f / (1.f + expf(-sp));
                r = sp * sg;
            } else {
                int w = (oo - 16) / 3;
                float sp = NORM_S * obF[(p * 64 + w) * 2 + s];
                float sg = 1.f / (1.f + expf(-sp));
                r = NORM_V * raw * sg;
            }
            fout[(size_t)(base + nn) * 64 + oo] = r;
        }
        __syncthreads();
    }
}

// ---------------------------------------------------------------------------
// Readout: energy[g] = sum_n (s[n]·w_out) * 0.25   grouped by batch_idx
// ---------------------------------------------------------------------------
__global__ __launch_bounds__(256) void readout_kernel(
    const float* __restrict__ f, const int* __restrict__ batch,
    const float* __restrict__ w, float* __restrict__ out)
{
    __shared__ float acc[N_GRAPHS];
    __shared__ float sw[16];
    int t = threadIdx.x;
    if (t < N_GRAPHS) acc[t] = 0.f;
    if (t < 16) sw[t] = w[t];
    __syncthreads();
    int n = blockIdx.x * 256 + t;
    if (n < N_NODES) {
        const float* fn = f + (size_t)n * 64;
        float val = 0.f;
        #pragma unroll
        for (int u = 0; u < 16; ++u) val += fn[u] * sw[u];
        atomicAdd(&acc[batch[n]], val * INV_LIN_OUT);
    }
    __syncthreads();
    if (t < N_GRAPHS && acc[t] != 0.f) atomicAdd(out + t, acc[t]);
}

// ---------------------------------------------------------------------------
extern "C" void kernel_launch(void* const* d_in, const int* in_sizes, int n_in,
                              void* d_out, int out_size)
{
    const float* x      = (const float*)d_in[0];
    const int*   row    = (const int*)  d_in[1];
    const int*   col    = (const int*)  d_in[2];
    const int*   batch  = (const int*)  d_in[3];
    const float* w_in0  = (const float*)d_in[4];
    const float* w_in1  = (const float*)d_in[5];
    const float* tpw    = (const float*)d_in[6];
    const float* w_out0 = (const float*)d_in[7];
    float* out = (float*)d_out;

    float *fa, *fb, *Fg;
    cudaGetSymbolAddress((void**)&fa, g_fa);
    cudaGetSymbolAddress((void**)&fb, g_fb);
    cudaGetSymbolAddress((void**)&Fg, g_F);

    proj_kernel<<<(N_NODES + 255) / 256, 256>>>(x, w_in0, w_in1, fa);

    float* cur = fa;
    float* nxt = fb;
    for (int l = 0; l < 3; ++l) {
        cudaMemsetAsync(Fg, 0, (size_t)N_NODES * 64 * sizeof(float));
        agg_kernel<<<(N_EDGES * 16 + 255) / 256, 256>>>(cur, row, col, Fg);
        tp_gate_kernel<<<1024, 256>>>(cur, Fg, tpw + (size_t)l * 5 * 4096, nxt);
        float* tmp = cur; cur = nxt; nxt = tmp;
    }

    cudaMemsetAsync(out, 0, N_GRAPHS * sizeof(float));
    readout_kernel<<<(N_NODES + 255) / 256, 256>>>(cur, batch, w_out0, out);
}